// round 1
// baseline (speedup 1.0000x reference)
#include <cuda_runtime.h>

// Q_net_3736621548252 — exact-zero propagation analysis:
//
// Layer-1 edge features occupy only channels [8:20) of the 40-channel node
// state (channels [0:8) and [20:40) are concatenated zero blocks). Layer 2's
// out0/out2 depend exclusively on node channels [0:8) and [20:40) (both exactly
// zero), so the second node state again has only channels [8:20) nonzero.
// Layer 3's energy head reads ONLY channels [0:8) and [20:40), which are
// exactly zero. Hence e_out == 0, node_out == 0, and the reference output is
// exactly zeros(NF) in fp32 — every product feeding the output carries an
// exact 0.0f factor and all operands are finite, so no NaN/Inf can leak in.
//
// The optimal correct kernel therefore writes out_size zeros (d_out is
// poisoned to 0xAA by the harness, so the write is required).

__global__ void q_net_zero_kernel(float* __restrict__ out, int n) {
    int i = blockIdx.x * blockDim.x + threadIdx.x;
    if (i < n) out[i] = 0.0f;
}

extern "C" void kernel_launch(void* const* d_in, const int* in_sizes, int n_in,
                              void* d_out, int out_size) {
    (void)d_in; (void)in_sizes; (void)n_in;
    float* out = (float*)d_out;
    int n = out_size;
    int threads = 64;
    int blocks = (n + threads - 1) / threads;
    if (blocks < 1) blocks = 1;
    q_net_zero_kernel<<<blocks, threads>>>(out, n);
}

// round 2
// speedup vs baseline: 1.4020x; 1.4020x over previous
#include <cuda_runtime.h>

// Q_net_3736621548252 — exact-zero propagation (see R0 analysis):
//
// Layer-1 populates only node channels [8:20); layer-2's surviving path (out1)
// again populates only [8:20); layer-3's energy head reads only channels
// [0:8) and [20:40), which are exactly fp32 zero. Every product feeding the
// output carries an exact 0.0f factor with finite co-factors, so the
// reference output is bit-exactly zeros(NF). rel_err = 0.0 confirmed in R1.
//
// R2 optimization: replace the user zero-kernel (whose 2.9us node time is
// pure dispatch overhead for 64 stores) with a native CUDA-graph MEMSET node
// via cudaMemsetAsync. memset(0) produces the identical 0.0f bit pattern.
// This removes the user-kernel launch path from the captured graph, leaving
// a single lightweight memset node — the minimal possible graph for this
// problem.

extern "C" void kernel_launch(void* const* d_in, const int* in_sizes, int n_in,
                              void* d_out, int out_size) {
    (void)d_in; (void)in_sizes; (void)n_in;
    // Graph-capturable: becomes a memset node. No allocation, no sync.
    cudaMemsetAsync(d_out, 0, (size_t)out_size * sizeof(float), 0);
}